// round 15
// baseline (speedup 1.0000x reference)
#include <cuda_runtime.h>
#include <cstdint>
#include <cstddef>

// Problem constants
#define BSZ 256      // batch
#define TT  512      // time steps
#define EE  256      // input dim
#define HH  256      // hidden dim
#define NB  2        // batches per cluster (scan)

typedef unsigned long long ull;

// ---- packed f32x2 helpers (Blackwell) -------------------------------------
__device__ __forceinline__ ull fma2(ull a, ull b, ull c) {
    ull d;
    asm("fma.rn.f32x2 %0, %1, %2, %3;" : "=l"(d) : "l"(a), "l"(b), "l"(c));
    return d;
}
__device__ __forceinline__ ull splat2(float x) {
    ull d;
    asm("mov.b64 %0, {%1, %1};" : "=l"(d) : "f"(x));
    return d;
}
__device__ __forceinline__ float2 unpack2(ull a) {
    float2 r;
    asm("mov.b64 {%0, %1}, %2;" : "=f"(r.x), "=f"(r.y) : "l"(a));
    return r;
}
__device__ __forceinline__ uint32_t smem_u32(const void* p) {
    uint32_t a;
    asm("{ .reg .u64 t; cvta.to.shared.u64 t, %1; cvt.u32.u64 %0, t; }"
        : "=r"(a) : "l"(p));
    return a;
}

// ---- one-MUFU transcendentals ([1,2] reciprocal seed) ----------------------
__device__ __forceinline__ float rcp_1to2(float d) {
    float r = fmaf(d, -0.47058824f, 1.4117647f);  // 24/17 - 8/17*d
    r = r * fmaf(-d, r, 2.0f);
    r = r * fmaf(-d, r, 2.0f);                    // err ~1.2e-5
    return r;
}
__device__ __forceinline__ float ftanh(float z) {
    const float az = fabsf(z);
    const float e = __expf(-2.0f * az);           // 1 MUFU
    const float r = rcp_1to2(1.0f + e);
    const float t = (1.0f - e) * r;
    return copysignf(t, z);
}
__device__ __forceinline__ float fsigmoid(float z) {
    const float az = fabsf(z);
    const float e = __expf(-az);                  // 1 MUFU
    const float r = rcp_1to2(1.0f + e);
    return (z >= 0.0f) ? r : e * r;
}

// ---------------------------------------------------------------------------
// Phase 1: gates = sigmoid(X @ Wx^T + b)  via packed-f32x2 SGEMM. (unchanged)
// ---------------------------------------------------------------------------
__global__ __launch_bounds__(256, 2) void gates_kernel(
    const float* __restrict__ X, const float* __restrict__ W,
    const float* __restrict__ bias, float* __restrict__ G)
{
    __shared__ __align__(16) float As[16][128];
    __shared__ __align__(16) float Ws[16][128];

    const int tid = threadIdx.x;
    const int bm = blockIdx.x * 128;
    const int bn = blockIdx.y * 128;
    const int tx = tid & 15;
    const int ty = tid >> 4;
    const int lr = tid >> 2;
    const int lc = (tid & 3) << 2;

    ull acc[8][4];
#pragma unroll
    for (int i = 0; i < 8; ++i)
#pragma unroll
        for (int jj = 0; jj < 4; ++jj) acc[i][jj] = 0ull;

    const float* Xp0 = X + (size_t)(bm + lr) * EE + lc;
    const float* Xp1 = X + (size_t)(bm + lr + 64) * EE + lc;
    const float* Wp0 = W + (size_t)(bn + lr) * EE + lc;
    const float* Wp1 = W + (size_t)(bn + lr + 64) * EE + lc;

    float4 pa0 = *(const float4*)(Xp0);
    float4 pa1 = *(const float4*)(Xp1);
    float4 pw0 = *(const float4*)(Wp0);
    float4 pw1 = *(const float4*)(Wp1);

#pragma unroll 1
    for (int k0 = 0; k0 < EE; k0 += 16) {
        __syncthreads();
        As[lc + 0][lr] = pa0.x; As[lc + 1][lr] = pa0.y;
        As[lc + 2][lr] = pa0.z; As[lc + 3][lr] = pa0.w;
        As[lc + 0][lr + 64] = pa1.x; As[lc + 1][lr + 64] = pa1.y;
        As[lc + 2][lr + 64] = pa1.z; As[lc + 3][lr + 64] = pa1.w;
        Ws[lc + 0][lr] = pw0.x; Ws[lc + 1][lr] = pw0.y;
        Ws[lc + 2][lr] = pw0.z; Ws[lc + 3][lr] = pw0.w;
        Ws[lc + 0][lr + 64] = pw1.x; Ws[lc + 1][lr + 64] = pw1.y;
        Ws[lc + 2][lr + 64] = pw1.z; Ws[lc + 3][lr + 64] = pw1.w;
        __syncthreads();

        if (k0 + 16 < EE) {
            pa0 = *(const float4*)(Xp0 + k0 + 16);
            pa1 = *(const float4*)(Xp1 + k0 + 16);
            pw0 = *(const float4*)(Wp0 + k0 + 16);
            pw1 = *(const float4*)(Wp1 + k0 + 16);
        }

#pragma unroll
        for (int k = 0; k < 16; ++k) {
            float a[8];
            *(float4*)&a[0] = *(const float4*)&As[k][ty * 8];
            *(float4*)&a[4] = *(const float4*)&As[k][ty * 8 + 4];
            ulonglong2 u0 = *(const ulonglong2*)&Ws[k][tx * 8];
            ulonglong2 u1 = *(const ulonglong2*)&Ws[k][tx * 8 + 4];
            const ull b0 = u0.x, b1 = u0.y, b2 = u1.x, b3 = u1.y;
#pragma unroll
            for (int i = 0; i < 8; ++i) {
                const ull s = splat2(a[i]);
                acc[i][0] = fma2(s, b0, acc[i][0]);
                acc[i][1] = fma2(s, b1, acc[i][1]);
                acc[i][2] = fma2(s, b2, acc[i][2]);
                acc[i][3] = fma2(s, b3, acc[i][3]);
            }
        }
    }

    float bb[8];
#pragma unroll
    for (int jj = 0; jj < 8; ++jj) bb[jj] = bias[bn + tx * 8 + jj];

#pragma unroll
    for (int i = 0; i < 8; ++i) {
        const size_t m = bm + ty * 8 + i;
        float v[8];
#pragma unroll
        for (int jj = 0; jj < 4; ++jj) {
            float2 z = unpack2(acc[i][jj]);
            v[2 * jj]     = fsigmoid(z.x + bb[2 * jj]);
            v[2 * jj + 1] = fsigmoid(z.y + bb[2 * jj + 1]);
        }
        float4 o0 = {v[0], v[1], v[2], v[3]};
        float4 o1 = {v[4], v[5], v[6], v[7]};
        *(float4*)(G + m * HH + bn + tx * 8)     = o0;
        *(float4*)(G + m * HH + bn + tx * 8 + 4) = o1;
    }
}

// ---------------------------------------------------------------------------
// Phase 2: MGU recurrence — full-row threads + 2 CTAs/SM latency hiding.
//   128 clusters x 2 CTAs = 256 CTAs of 128 threads (2 co-resident per SM:
//   independent clusters, so one CTA's waits hide under the other's FMA).
//   NB=2 batches per cluster. CTA rank r owns rows [r*128, +128); thread tid
//   owns row jg = r*128 + tid with its FULL W row (256 floats = 128 regs) and
//   computes COMPLETE dot products for both batches: no psum, no shfl, no
//   cross-thread reduce, h_prev in registers.
//   h buffer: hsh[2][NB][HH] — matvec reads are pure warp-broadcast LDS.128.
//   Per step: wait mb[p] (count 8 = 4 local + 4 peer warp arrivals, parity,
//   acquire.cluster) -> matvec (64 iters: 4 fma2 + 2 LDS.128) -> 2x tanh +
//   update -> 2x st.cluster (peer) + 2x STS (local) -> __syncwarp -> lane0
//   arrives local mb[q] + peer mb[q] (release.cluster) -> 2x STG out.
//   NO __syncthreads in the loop: the count-8 wait orders both local and
//   peer traffic (every warp's arrival at t-1 is posted after its reads of
//   the buffer written at t — same transitive WAR closure as R13).
// ---------------------------------------------------------------------------
__global__ void __cluster_dims__(2, 1, 1) __launch_bounds__(128, 2)
mgu_scan(const float* __restrict__ Whw, const float* __restrict__ Whb,
         float* out)
{
    __shared__ __align__(16) float hsh[2][NB][HH];   // 4 KB ping-pong h
    __shared__ __align__(8)  ull  bars[2];

    const int tid = threadIdx.x;          // 0..127 == row within CTA half
    uint32_t rank;
    asm("mov.u32 %0, %%cluster_ctarank;" : "=r"(rank));
    const int jg = (int)rank * 128 + tid;            // global row
    const int bbase = (blockIdx.x >> 1) * NB;        // cluster's batch pair

    // --- FULL W row (256 floats) into 128 packed registers ---
    ull wv[128];
    {
        const ulonglong2* wp = (const ulonglong2*)(Whw + (size_t)jg * HH);
#pragma unroll
        for (int i = 0; i < 64; ++i) {
            ulonglong2 v = wp[i];
            wv[2 * i] = v.x; wv[2 * i + 1] = v.y;
        }
    }

    for (int i = tid; i < 2 * NB * HH; i += 128)
        ((float*)hsh)[i] = 0.0f;

    if (tid == 0) {
        asm volatile("mbarrier.init.shared.b64 [%0], 8;"
                     :: "r"(smem_u32(&bars[0])) : "memory");
        asm volatile("mbarrier.init.shared.b64 [%0], 8;"
                     :: "r"(smem_u32(&bars[1])) : "memory");
    }

    const float biasr = Whb[jg];

    // out pointers for the 2 owned (batch,row) streams
    float* po0 = out + (size_t)(bbase + 0) * TT * HH + jg;
    float* po1 = out + (size_t)(bbase + 1) * TT * HH + jg;

    float gc0 = po0[0], gc1 = po1[0];     // gates t=0
    float hc0 = 0.0f, hc1 = 0.0f;         // persistent h (registers)

    // cluster addresses
    const uint32_t hl  = smem_u32(hsh);
    const uint32_t bl0 = smem_u32(&bars[0]);
    uint32_t hr, br0;
    asm("mapa.shared::cluster.u32 %0, %1, %2;"
        : "=r"(hr) : "r"(hl), "r"(rank ^ 1u));
    asm("mapa.shared::cluster.u32 %0, %1, %2;"
        : "=r"(br0) : "r"(bl0), "r"(rank ^ 1u));

    const bool lane0 = ((tid & 31) == 0);

    __syncthreads();
    // one-time: both CTAs' smem + mbarrier init visible cluster-wide
    asm volatile("barrier.cluster.arrive.aligned;" ::: "memory");
    asm volatile("barrier.cluster.wait.aligned;"   ::: "memory");

    uint32_t ph0 = 0, ph1 = 0;

#pragma unroll 1
    for (int t = 0; t < TT; ++t) {
        const int p = t & 1;
        const int q = p ^ 1;
        const bool not_last = (t + 1 < TT);

        // prefetch gates for t+1 (issued before the wait)
        float gn0 = 0.f, gn1 = 0.f;
        if (not_last) {
            const size_t o = (size_t)(t + 1) * HH;
            gn0 = po0[o]; gn1 = po1[o];
        }

        // step barrier: 8 warp-arrivals (4 local + 4 peer) of step t-1
        if (t > 0) {
            const uint32_t mb = bl0 + (uint32_t)p * 8u;
            const uint32_t par = p ? ph1 : ph0;
            uint32_t done;
            do {
                asm volatile(
                    "{\n\t.reg .pred P;\n\t"
                    "mbarrier.try_wait.parity.acquire.cluster.shared::cta.b64 "
                    "P, [%1], %2, 0x989680;\n\t"
                    "selp.b32 %0, 1, 0, P;\n\t}"
                    : "=r"(done) : "r"(mb), "r"(par) : "memory");
            } while (!done);
            if (p) ph1 ^= 1; else ph0 ^= 1;
        }

        // ---- full-K matvec for 2 batches (warp-broadcast LDS) ----
        const ulonglong2* x0 = (const ulonglong2*)&hsh[p][0][0];
        const ulonglong2* x1 = (const ulonglong2*)&hsh[p][1][0];
        ull a0 = 0, a1 = 0;
#pragma unroll
        for (int i = 0; i < 64; ++i) {
            const ulonglong2 v0 = x0[i];
            const ulonglong2 v1 = x1[i];
            const ull wA = wv[2 * i], wB = wv[2 * i + 1];
            a0 = fma2(wA, v0.x, a0);
            a1 = fma2(wA, v1.x, a1);
            a0 = fma2(wB, v0.y, a0);
            a1 = fma2(wB, v1.y, a1);
        }
        float2 u0 = unpack2(a0);
        float2 u1 = unpack2(a1);
        const float z0 = (u0.x + u0.y) + biasr;
        const float z1 = (u1.x + u1.y) + biasr;

        // ---- update (h_prev in registers) ----
        const float th0 = ftanh(z0);
        const float th1 = ftanh(z1);
        hc0 = fmaf(gc0, hc0 - th0, th0);   // g*h + (1-g)*tanh
        hc1 = fmaf(gc1, hc1 - th1, th1);
        gc0 = gn0; gc1 = gn1;

        if (not_last) {
            // peer DSMEM stores first (longest flight), then local STS
            const uint32_t ra0 = hr + (uint32_t)((q * NB) * HH + jg) * 4u;
            asm volatile("st.shared::cluster.f32 [%0], %1;"
                         :: "r"(ra0), "f"(hc0) : "memory");
            asm volatile("st.shared::cluster.f32 [%0], %1;"
                         :: "r"(ra0 + (uint32_t)(HH * 4)), "f"(hc1)
                         : "memory");
            hsh[q][0][jg] = hc0;
            hsh[q][1][jg] = hc1;
            __syncwarp();
            if (lane0) {   // warp-aggregated arrivals: local + peer mb[q]
                const uint32_t off = (uint32_t)q * 8u;
                asm volatile(
                    "mbarrier.arrive.release.cluster.shared::cta.b64 _, [%0];"
                    :: "r"(bl0 + off) : "memory");
                asm volatile(
                    "mbarrier.arrive.release.cluster.shared::cluster.b64 _, [%0];"
                    :: "r"(br0 + off) : "memory");
            }
        }

        // global out stores (gate nothing)
        const size_t ot = (size_t)t * HH;
        po0[ot] = hc0;
        po1[ot] = hc1;
    }

    // Trailing cluster sync: no CTA exits while peer DSMEM traffic may be
    // in flight toward it.
    asm volatile("barrier.cluster.arrive.aligned;" ::: "memory");
    asm volatile("barrier.cluster.wait.aligned;"   ::: "memory");
}

// ---------------------------------------------------------------------------
extern "C" void kernel_launch(void* const* d_in, const int* in_sizes, int n_in,
                              void* d_out, int out_size)
{
    const float* x   = (const float*)d_in[0];  // [B,T,E]
    const float* Wxw = (const float*)d_in[1];  // [H,E]
    const float* Wxb = (const float*)d_in[2];  // [H]
    const float* Whw = (const float*)d_in[3];  // [H,H]
    const float* Whb = (const float*)d_in[4];  // [H]
    float* out = (float*)d_out;                // [B,T,H]

    dim3 g1(BSZ * TT / 128, HH / 128);
    gates_kernel<<<g1, 256>>>(x, Wxw, Wxb, out);

    // 128 clusters x 2 CTAs x 128 threads; 2 CTAs co-resident per SM
    mgu_scan<<<(BSZ / NB) * 2, 128>>>(Whw, Whb, out);
}

// round 16
// speedup vs baseline: 2.1939x; 2.1939x over previous
#include <cuda_runtime.h>
#include <cstdint>
#include <cstddef>

// Problem constants
#define BSZ 256      // batch
#define TT  512      // time steps
#define EE  256      // input dim
#define HH  256      // hidden dim
#define NB  4        // batches per cluster

typedef unsigned long long ull;

// ---- packed f32x2 helpers (Blackwell) -------------------------------------
__device__ __forceinline__ ull fma2(ull a, ull b, ull c) {
    ull d;
    asm("fma.rn.f32x2 %0, %1, %2, %3;" : "=l"(d) : "l"(a), "l"(b), "l"(c));
    return d;
}
__device__ __forceinline__ ull splat2(float x) {
    ull d;
    asm("mov.b64 %0, {%1, %1};" : "=l"(d) : "f"(x));
    return d;
}
__device__ __forceinline__ float2 unpack2(ull a) {
    float2 r;
    asm("mov.b64 {%0, %1}, %2;" : "=f"(r.x), "=f"(r.y) : "l"(a));
    return r;
}
__device__ __forceinline__ uint32_t smem_u32(const void* p) {
    uint32_t a;
    asm("{ .reg .u64 t; cvta.to.shared.u64 t, %1; cvt.u32.u64 %0, t; }"
        : "=r"(a) : "l"(p));
    return a;
}

// ---- one-MUFU transcendentals ([1,2] reciprocal seed) ----------------------
__device__ __forceinline__ float rcp_1to2(float d) {
    float r = fmaf(d, -0.47058824f, 1.4117647f);  // 24/17 - 8/17*d
    r = r * fmaf(-d, r, 2.0f);
    r = r * fmaf(-d, r, 2.0f);                    // err ~1.2e-5
    return r;
}
__device__ __forceinline__ float ftanh(float z) {
    const float az = fabsf(z);
    const float e = __expf(-2.0f * az);           // 1 MUFU
    const float r = rcp_1to2(1.0f + e);
    const float t = (1.0f - e) * r;
    return copysignf(t, z);
}
__device__ __forceinline__ float fsigmoid(float z) {
    const float az = fabsf(z);
    const float e = __expf(-az);                  // 1 MUFU
    const float r = rcp_1to2(1.0f + e);
    return (z >= 0.0f) ? r : e * r;
}

// ---------------------------------------------------------------------------
// Phase 1: gates = sigmoid(X @ Wx^T + b)  via packed-f32x2 SGEMM. (unchanged)
// ---------------------------------------------------------------------------
__global__ __launch_bounds__(256, 2) void gates_kernel(
    const float* __restrict__ X, const float* __restrict__ W,
    const float* __restrict__ bias, float* __restrict__ G)
{
    __shared__ __align__(16) float As[16][128];
    __shared__ __align__(16) float Ws[16][128];

    const int tid = threadIdx.x;
    const int bm = blockIdx.x * 128;
    const int bn = blockIdx.y * 128;
    const int tx = tid & 15;
    const int ty = tid >> 4;
    const int lr = tid >> 2;
    const int lc = (tid & 3) << 2;

    ull acc[8][4];
#pragma unroll
    for (int i = 0; i < 8; ++i)
#pragma unroll
        for (int jj = 0; jj < 4; ++jj) acc[i][jj] = 0ull;

    const float* Xp0 = X + (size_t)(bm + lr) * EE + lc;
    const float* Xp1 = X + (size_t)(bm + lr + 64) * EE + lc;
    const float* Wp0 = W + (size_t)(bn + lr) * EE + lc;
    const float* Wp1 = W + (size_t)(bn + lr + 64) * EE + lc;

    float4 pa0 = *(const float4*)(Xp0);
    float4 pa1 = *(const float4*)(Xp1);
    float4 pw0 = *(const float4*)(Wp0);
    float4 pw1 = *(const float4*)(Wp1);

#pragma unroll 1
    for (int k0 = 0; k0 < EE; k0 += 16) {
        __syncthreads();
        As[lc + 0][lr] = pa0.x; As[lc + 1][lr] = pa0.y;
        As[lc + 2][lr] = pa0.z; As[lc + 3][lr] = pa0.w;
        As[lc + 0][lr + 64] = pa1.x; As[lc + 1][lr + 64] = pa1.y;
        As[lc + 2][lr + 64] = pa1.z; As[lc + 3][lr + 64] = pa1.w;
        Ws[lc + 0][lr] = pw0.x; Ws[lc + 1][lr] = pw0.y;
        Ws[lc + 2][lr] = pw0.z; Ws[lc + 3][lr] = pw0.w;
        Ws[lc + 0][lr + 64] = pw1.x; Ws[lc + 1][lr + 64] = pw1.y;
        Ws[lc + 2][lr + 64] = pw1.z; Ws[lc + 3][lr + 64] = pw1.w;
        __syncthreads();

        if (k0 + 16 < EE) {
            pa0 = *(const float4*)(Xp0 + k0 + 16);
            pa1 = *(const float4*)(Xp1 + k0 + 16);
            pw0 = *(const float4*)(Wp0 + k0 + 16);
            pw1 = *(const float4*)(Wp1 + k0 + 16);
        }

#pragma unroll
        for (int k = 0; k < 16; ++k) {
            float a[8];
            *(float4*)&a[0] = *(const float4*)&As[k][ty * 8];
            *(float4*)&a[4] = *(const float4*)&As[k][ty * 8 + 4];
            ulonglong2 u0 = *(const ulonglong2*)&Ws[k][tx * 8];
            ulonglong2 u1 = *(const ulonglong2*)&Ws[k][tx * 8 + 4];
            const ull b0 = u0.x, b1 = u0.y, b2 = u1.x, b3 = u1.y;
#pragma unroll
            for (int i = 0; i < 8; ++i) {
                const ull s = splat2(a[i]);
                acc[i][0] = fma2(s, b0, acc[i][0]);
                acc[i][1] = fma2(s, b1, acc[i][1]);
                acc[i][2] = fma2(s, b2, acc[i][2]);
                acc[i][3] = fma2(s, b3, acc[i][3]);
            }
        }
    }

    float bb[8];
#pragma unroll
    for (int jj = 0; jj < 8; ++jj) bb[jj] = bias[bn + tx * 8 + jj];

#pragma unroll
    for (int i = 0; i < 8; ++i) {
        const size_t m = bm + ty * 8 + i;
        float v[8];
#pragma unroll
        for (int jj = 0; jj < 4; ++jj) {
            float2 z = unpack2(acc[i][jj]);
            v[2 * jj]     = fsigmoid(z.x + bb[2 * jj]);
            v[2 * jj + 1] = fsigmoid(z.y + bb[2 * jj + 1]);
        }
        float4 o0 = {v[0], v[1], v[2], v[3]};
        float4 o1 = {v[4], v[5], v[6], v[7]};
        *(float4*)(G + m * HH + bn + tx * 8)     = o0;
        *(float4*)(G + m * HH + bn + tx * 8 + 4) = o1;
    }
}

// ---------------------------------------------------------------------------
// Phase 2: MGU recurrence — R13 protocol at 512 threads (K-eighths).
//   Cluster(2) x 64, NB=4, 512 steps. CTA rank r owns rows [r*128, +128).
//   512 threads: j2 = tid&63 -> rows {jg0 = r*128+j2, jg1 = jg0+64};
//   ke = tid>>6 in 0..7 -> K-eighth [ke*32, ke*32+32) (warp-granular:
//   ke = warp>>1). W per thread: 2 rows x 32 k = 32 ull = 64 regs (R15's
//   fatal 256-reg mistake halved twice; total ~120 regs, fits 128 cap).
//   16 warps = 4/SMSP: doubles latency hiding over R13 (same FMA floor
//   1024 cyc/step, same 512 LDS wavefronts, 4:1 fma2:LDS kept per-iter).
//   Protocol = R13 verbatim: remote-K warps (ke>>2 != rank) wait mb[p]
//   (count 16 = all peer warps' early arrives) -> matvec -> psum[e][ke][j2]
//   (coalesced both ways) -> BAR1 -> thread owns stream e == ke: 8 coalesced
//   LDS reduce + 1 tanh + update (h in register) -> st.cluster + STS + STG
//   -> syncwarp -> lane0 posts arrive.release on PEER mb[q] -> BAR2.
// ---------------------------------------------------------------------------
__global__ void __cluster_dims__(2, 1, 1) __launch_bounds__(512, 1)
mgu_scan(const float* __restrict__ Whw, const float* __restrict__ Whb,
         float* out)
{
    __shared__ __align__(16) float hsh[2][NB][HH];     // 8 KB ping-pong h
    __shared__ __align__(16) float psum[8][8][64];     // 16 KB [e][ke][j2]
    __shared__ __align__(8)  ull  bars[2];

    const int tid = threadIdx.x;
    const int j2 = tid & 63;
    const int ke = tid >> 6;                 // K-eighth, warp-granular
    uint32_t rank;
    asm("mov.u32 %0, %%cluster_ctarank;" : "=r"(rank));
    const int jg0 = (int)rank * 128 + j2;
    const int jg1 = jg0 + 64;
    const int bbase = (blockIdx.x >> 1) * NB;
    // K-eighth [ke*32..) holds h-entries produced by CTA (ke>>2)
    const bool remote_k = ((uint32_t)(ke >> 2) != rank);

    // --- W rows (2 j, this K eighth = 32 floats each) into 32 ull regs ---
    ull wv0[16], wv1[16];
    {
        const ulonglong2* wp0 =
            (const ulonglong2*)(Whw + (size_t)jg0 * HH + ke * 32);
        const ulonglong2* wp1 =
            (const ulonglong2*)(Whw + (size_t)jg1 * HH + ke * 32);
#pragma unroll
        for (int i = 0; i < 8; ++i) {
            ulonglong2 a = wp0[i], b = wp1[i];
            wv0[2 * i] = a.x; wv0[2 * i + 1] = a.y;
            wv1[2 * i] = b.x; wv1[2 * i + 1] = b.y;
        }
    }

    for (int i = tid; i < 2 * NB * HH; i += 512)
        ((float*)hsh)[i] = 0.0f;

    if (tid == 0) {
        asm volatile("mbarrier.init.shared.b64 [%0], 16;"
                     :: "r"(smem_u32(&bars[0])) : "memory");
        asm volatile("mbarrier.init.shared.b64 [%0], 16;"
                     :: "r"(smem_u32(&bars[1])) : "memory");
    }

    // ---- ownership: this thread finalizes stream e == ke ----
    // e = rowhalf*4 + b  (rowhalf: 0 -> jg0, 1 -> jg1)
    const int rowhalf = ke >> 2;
    const int jrow = rowhalf ? jg1 : jg0;
    const int bown = ke & 3;
    const float biasr = Whb[jrow];

    // out pointer for the owned (batch,row) stream
    float* po = out + (size_t)(bbase + bown) * TT * HH + jrow;

    float gc = po[0];                 // gate t=0
    float hcr = 0.0f;                 // persistent h (register)

    // cluster addresses
    const uint32_t hl = smem_u32(hsh);
    const uint32_t bl0 = smem_u32(&bars[0]);
    uint32_t hr, br0;
    asm("mapa.shared::cluster.u32 %0, %1, %2;"
        : "=r"(hr) : "r"(hl), "r"(rank ^ 1u));
    asm("mapa.shared::cluster.u32 %0, %1, %2;"
        : "=r"(br0) : "r"(bl0), "r"(rank ^ 1u));

    const bool lane0 = ((tid & 31) == 0);

    __syncthreads();
    // one-time: both CTAs' smem init + mbarrier init visible cluster-wide
    asm volatile("barrier.cluster.arrive.aligned;" ::: "memory");
    asm volatile("barrier.cluster.wait.aligned;"   ::: "memory");

    uint32_t ph0 = 0, ph1 = 0;

#pragma unroll 1
    for (int t = 0; t < TT; ++t) {
        const int p = t & 1;
        const int q = p ^ 1;
        const bool not_last = (t + 1 < TT);

        // prefetch gate for t+1 (issued before any waiting)
        float gn = 0.f;
        if (not_last) gn = po[(size_t)(t + 1) * HH];

        // remote-K warps wait for the peer's 16 warp-arrivals into buffer p
        if (t > 0 && remote_k) {
            const uint32_t mb = bl0 + (uint32_t)p * 8u;
            const uint32_t par = p ? ph1 : ph0;
            uint32_t done;
            do {
                asm volatile(
                    "{\n\t.reg .pred P;\n\t"
                    "mbarrier.try_wait.parity.acquire.cluster.shared::cta.b64 "
                    "P, [%1], %2, 0x989680;\n\t"
                    "selp.b32 %0, 1, 0, P;\n\t}"
                    : "=r"(done) : "r"(mb), "r"(par) : "memory");
            } while (!done);
        }
        if (t > 0) { if (p) ph1 ^= 1; else ph0 ^= 1; }

        // ---- matvec over this thread's K-eighth (32 elems = 8 x 4) ----
        const float* hb = &hsh[p][0][ke * 32];
        const ulonglong2* x0 = (const ulonglong2*)(hb);
        const ulonglong2* x1 = (const ulonglong2*)(hb + HH);
        const ulonglong2* x2 = (const ulonglong2*)(hb + 2 * HH);
        const ulonglong2* x3 = (const ulonglong2*)(hb + 3 * HH);
        ull a00 = 0, a01 = 0, a02 = 0, a03 = 0;   // row jg0, batches 0..3
        ull a10 = 0, a11 = 0, a12 = 0, a13 = 0;   // row jg1
#pragma unroll
        for (int i = 0; i < 8; ++i) {
            const ulonglong2 v0 = x0[i];
            const ulonglong2 v1 = x1[i];
            const ulonglong2 v2 = x2[i];
            const ulonglong2 v3 = x3[i];
            const ull wA0 = wv0[2 * i], wB0 = wv0[2 * i + 1];
            const ull wA1 = wv1[2 * i], wB1 = wv1[2 * i + 1];
            a00 = fma2(wA0, v0.x, a00); a01 = fma2(wA0, v1.x, a01);
            a02 = fma2(wA0, v2.x, a02); a03 = fma2(wA0, v3.x, a03);
            a10 = fma2(wA1, v0.x, a10); a11 = fma2(wA1, v1.x, a11);
            a12 = fma2(wA1, v2.x, a12); a13 = fma2(wA1, v3.x, a13);
            a00 = fma2(wB0, v0.y, a00); a01 = fma2(wB0, v1.y, a01);
            a02 = fma2(wB0, v2.y, a02); a03 = fma2(wB0, v3.y, a03);
            a10 = fma2(wB1, v0.y, a10); a11 = fma2(wB1, v1.y, a11);
            a12 = fma2(wB1, v2.y, a12); a13 = fma2(wB1, v3.y, a13);
        }
        // pair-sum + publish partials: psum[e][ke][j2] (coalesced stores)
        {
            float r[8];
            float2 u;
            u = unpack2(a00); r[0] = u.x + u.y;
            u = unpack2(a01); r[1] = u.x + u.y;
            u = unpack2(a02); r[2] = u.x + u.y;
            u = unpack2(a03); r[3] = u.x + u.y;
            u = unpack2(a10); r[4] = u.x + u.y;
            u = unpack2(a11); r[5] = u.x + u.y;
            u = unpack2(a12); r[6] = u.x + u.y;
            u = unpack2(a13); r[7] = u.x + u.y;
#pragma unroll
            for (int e = 0; e < 8; ++e)
                psum[e][ke][j2] = r[e];
        }
        __syncthreads();   // BAR1: psum visible; propagates mb-wait ordering

        // ---- assigned reduce + update (1 stream: e == ke) ----
        float z = biasr;
#pragma unroll
        for (int k = 0; k < 8; ++k) z += psum[ke][k][j2];
        const float th = ftanh(z);
        hcr = fmaf(gc, hcr - th, th);    // g*h + (1-g)*tanh
        gc = gn;

        if (not_last) {
            // peer DSMEM store first (longest flight), then local STS
            const uint32_t ra = hr +
                (uint32_t)(((q * NB + bown) * HH + jrow) * 4);
            asm volatile("st.shared::cluster.f32 [%0], %1;"
                         :: "r"(ra), "f"(hcr) : "memory");
            hsh[q][bown][jrow] = hcr;
            __syncwarp();
            if (lane0) {     // warp-aggregated early remote arrive
                asm volatile(
                    "mbarrier.arrive.release.cluster.shared::cluster.b64 _, [%0];"
                    :: "r"(br0 + (uint32_t)q * 8u) : "memory");
            }
        }

        // global out store (gates nothing)
        po[(size_t)t * HH] = hcr;

        __syncthreads();   // BAR2: local h-half ordered for next step
    }

    // Trailing cluster sync: no CTA exits while peer DSMEM traffic may be
    // in flight toward it.
    asm volatile("barrier.cluster.arrive.aligned;" ::: "memory");
    asm volatile("barrier.cluster.wait.aligned;"   ::: "memory");
}

// ---------------------------------------------------------------------------
extern "C" void kernel_launch(void* const* d_in, const int* in_sizes, int n_in,
                              void* d_out, int out_size)
{
    const float* x   = (const float*)d_in[0];  // [B,T,E]
    const float* Wxw = (const float*)d_in[1];  // [H,E]
    const float* Wxb = (const float*)d_in[2];  // [H]
    const float* Whw = (const float*)d_in[3];  // [H,H]
    const float* Whb = (const float*)d_in[4];  // [H]
    float* out = (float*)d_out;                // [B,T,H]

    dim3 g1(BSZ * TT / 128, HH / 128);
    gates_kernel<<<g1, 256>>>(x, Wxw, Wxb, out);

    mgu_scan<<<(BSZ / NB) * 2, 512>>>(Whw, Whb, out);
}

// round 17
// speedup vs baseline: 2.2653x; 1.0326x over previous
#include <cuda_runtime.h>
#include <cstdint>
#include <cstddef>

// Problem constants
#define BSZ 256      // batch
#define TT  512      // time steps
#define EE  256      // input dim
#define HH  256      // hidden dim
#define NB  4        // batches per cluster

typedef unsigned long long ull;

// ---- packed f32x2 helpers (Blackwell) -------------------------------------
__device__ __forceinline__ ull fma2(ull a, ull b, ull c) {
    ull d;
    asm("fma.rn.f32x2 %0, %1, %2, %3;" : "=l"(d) : "l"(a), "l"(b), "l"(c));
    return d;
}
__device__ __forceinline__ ull splat2(float x) {
    ull d;
    asm("mov.b64 %0, {%1, %1};" : "=l"(d) : "f"(x));
    return d;
}
__device__ __forceinline__ float2 unpack2(ull a) {
    float2 r;
    asm("mov.b64 {%0, %1}, %2;" : "=f"(r.x), "=f"(r.y) : "l"(a));
    return r;
}
__device__ __forceinline__ uint32_t smem_u32(const void* p) {
    uint32_t a;
    asm("{ .reg .u64 t; cvta.to.shared.u64 t, %1; cvt.u32.u64 %0, t; }"
        : "=r"(a) : "l"(p));
    return a;
}

// ---- one-MUFU transcendentals ([1,2] reciprocal seed) ----------------------
__device__ __forceinline__ float rcp_1to2(float d) {
    float r = fmaf(d, -0.47058824f, 1.4117647f);  // 24/17 - 8/17*d
    r = r * fmaf(-d, r, 2.0f);
    r = r * fmaf(-d, r, 2.0f);                    // err ~1.2e-5
    return r;
}
__device__ __forceinline__ float ftanh(float z) {
    const float az = fabsf(z);
    const float e = __expf(-2.0f * az);           // 1 MUFU
    const float r = rcp_1to2(1.0f + e);
    const float t = (1.0f - e) * r;
    return copysignf(t, z);
}
__device__ __forceinline__ float fsigmoid(float z) {
    const float az = fabsf(z);
    const float e = __expf(-az);                  // 1 MUFU
    const float r = rcp_1to2(1.0f + e);
    return (z >= 0.0f) ? r : e * r;
}

// ---------------------------------------------------------------------------
// Phase 1: gates = sigmoid(X @ Wx^T + b) — DOUBLE-BUFFERED packed-f32x2 SGEMM.
//   128x128 CTA tile, BK=16, 8x8 register tile, 256 threads, 2 CTAs/SM.
//   One __syncthreads per k-tile (was two): store next tile into buf[cur^1]
//   while this tile computes on buf[cur]. Safe: a warp writes buf[cur^1]
//   only after passing the previous sync, which all warps reached after
//   finishing compute on that buffer.
// ---------------------------------------------------------------------------
__global__ __launch_bounds__(256, 2) void gates_kernel(
    const float* __restrict__ X, const float* __restrict__ W,
    const float* __restrict__ bias, float* __restrict__ G)
{
    __shared__ __align__(16) float As[2][16][128];
    __shared__ __align__(16) float Ws[2][16][128];

    const int tid = threadIdx.x;
    const int bm = blockIdx.x * 128;
    const int bn = blockIdx.y * 128;
    const int tx = tid & 15;
    const int ty = tid >> 4;
    const int lr = tid >> 2;
    const int lc = (tid & 3) << 2;

    ull acc[8][4];
#pragma unroll
    for (int i = 0; i < 8; ++i)
#pragma unroll
        for (int jj = 0; jj < 4; ++jj) acc[i][jj] = 0ull;

    const float* Xp0 = X + (size_t)(bm + lr) * EE + lc;
    const float* Xp1 = X + (size_t)(bm + lr + 64) * EE + lc;
    const float* Wp0 = W + (size_t)(bn + lr) * EE + lc;
    const float* Wp1 = W + (size_t)(bn + lr + 64) * EE + lc;

    // tile 0 -> registers -> smem buf 0
    float4 pa0 = *(const float4*)(Xp0);
    float4 pa1 = *(const float4*)(Xp1);
    float4 pw0 = *(const float4*)(Wp0);
    float4 pw1 = *(const float4*)(Wp1);
    As[0][lc + 0][lr] = pa0.x; As[0][lc + 1][lr] = pa0.y;
    As[0][lc + 2][lr] = pa0.z; As[0][lc + 3][lr] = pa0.w;
    As[0][lc + 0][lr + 64] = pa1.x; As[0][lc + 1][lr + 64] = pa1.y;
    As[0][lc + 2][lr + 64] = pa1.z; As[0][lc + 3][lr + 64] = pa1.w;
    Ws[0][lc + 0][lr] = pw0.x; Ws[0][lc + 1][lr] = pw0.y;
    Ws[0][lc + 2][lr] = pw0.z; Ws[0][lc + 3][lr] = pw0.w;
    Ws[0][lc + 0][lr + 64] = pw1.x; Ws[0][lc + 1][lr + 64] = pw1.y;
    Ws[0][lc + 2][lr + 64] = pw1.z; Ws[0][lc + 3][lr + 64] = pw1.w;
    __syncthreads();

    int cur = 0;
#pragma unroll 1
    for (int k0 = 0; k0 < EE; k0 += 16) {
        const bool has_next = (k0 + 16 < EE);
        if (has_next) {   // global prefetch (latency hides under compute)
            pa0 = *(const float4*)(Xp0 + k0 + 16);
            pa1 = *(const float4*)(Xp1 + k0 + 16);
            pw0 = *(const float4*)(Wp0 + k0 + 16);
            pw1 = *(const float4*)(Wp1 + k0 + 16);
        }

#pragma unroll
        for (int k = 0; k < 16; ++k) {
            float a[8];
            *(float4*)&a[0] = *(const float4*)&As[cur][k][ty * 8];
            *(float4*)&a[4] = *(const float4*)&As[cur][k][ty * 8 + 4];
            ulonglong2 u0 = *(const ulonglong2*)&Ws[cur][k][tx * 8];
            ulonglong2 u1 = *(const ulonglong2*)&Ws[cur][k][tx * 8 + 4];
            const ull b0 = u0.x, b1 = u0.y, b2 = u1.x, b3 = u1.y;
#pragma unroll
            for (int i = 0; i < 8; ++i) {
                const ull s = splat2(a[i]);
                acc[i][0] = fma2(s, b0, acc[i][0]);
                acc[i][1] = fma2(s, b1, acc[i][1]);
                acc[i][2] = fma2(s, b2, acc[i][2]);
                acc[i][3] = fma2(s, b3, acc[i][3]);
            }
        }

        if (has_next) {   // stage next tile into the other buffer
            const int nxt = cur ^ 1;
            As[nxt][lc + 0][lr] = pa0.x; As[nxt][lc + 1][lr] = pa0.y;
            As[nxt][lc + 2][lr] = pa0.z; As[nxt][lc + 3][lr] = pa0.w;
            As[nxt][lc + 0][lr + 64] = pa1.x; As[nxt][lc + 1][lr + 64] = pa1.y;
            As[nxt][lc + 2][lr + 64] = pa1.z; As[nxt][lc + 3][lr + 64] = pa1.w;
            Ws[nxt][lc + 0][lr] = pw0.x; Ws[nxt][lc + 1][lr] = pw0.y;
            Ws[nxt][lc + 2][lr] = pw0.z; Ws[nxt][lc + 3][lr] = pw0.w;
            Ws[nxt][lc + 0][lr + 64] = pw1.x; Ws[nxt][lc + 1][lr + 64] = pw1.y;
            Ws[nxt][lc + 2][lr + 64] = pw1.z; Ws[nxt][lc + 3][lr + 64] = pw1.w;
            __syncthreads();
            cur = nxt;
        }
    }

    float bb[8];
#pragma unroll
    for (int jj = 0; jj < 8; ++jj) bb[jj] = bias[bn + tx * 8 + jj];

#pragma unroll
    for (int i = 0; i < 8; ++i) {
        const size_t m = bm + ty * 8 + i;
        float v[8];
#pragma unroll
        for (int jj = 0; jj < 4; ++jj) {
            float2 z = unpack2(acc[i][jj]);
            v[2 * jj]     = fsigmoid(z.x + bb[2 * jj]);
            v[2 * jj + 1] = fsigmoid(z.y + bb[2 * jj + 1]);
        }
        float4 o0 = {v[0], v[1], v[2], v[3]};
        float4 o1 = {v[4], v[5], v[6], v[7]};
        *(float4*)(G + m * HH + bn + tx * 8)     = o0;
        *(float4*)(G + m * HH + bn + tx * 8 + 4) = o1;
    }
}

// ---------------------------------------------------------------------------
// Phase 2: MGU recurrence — R13 CHAMPION, verbatim (791.6us).
//   Cluster(2) x 64, NB=4, 512 steps; 256 threads: j2 = tid&63 -> rows
//   {jg0, jg1=jg0+64}; kq = tid>>6 -> K-quarter (warp-granular wait roles).
//   psum [e][kq][j2] coalesced both directions; remote-K warps wait the
//   count-8 mb (peer early warp-aggregated arrives); BAR1 -> assigned
//   reduce+update -> st.cluster + STS + syncwarp + lane0 peer arrive ->
//   STG -> BAR2.
// ---------------------------------------------------------------------------
__global__ void __cluster_dims__(2, 1, 1) __launch_bounds__(256, 1)
mgu_scan(const float* __restrict__ Whw, const float* __restrict__ Whb,
         float* out)
{
    __shared__ __align__(16) float hsh[2][NB][HH];      // 8 KB ping-pong h
    __shared__ __align__(16) float psum[8][4][64];      // 8 KB [e][kq][j2]
    __shared__ __align__(8)  ull  bars[2];

    const int tid = threadIdx.x;
    const int j2 = tid & 63;
    const int kq = tid >> 6;
    uint32_t rank;
    asm("mov.u32 %0, %%cluster_ctarank;" : "=r"(rank));
    const int jg0 = (int)rank * 128 + j2;
    const int jg1 = jg0 + 64;
    const int bbase = (blockIdx.x >> 1) * NB;
    // K-quarter [kq*64..) holds h-entries produced by CTA (kq>>1)
    const bool remote_k = ((uint32_t)(kq >> 1) != rank);

    // --- W rows (2 j, this K quarter) into 64 packed registers ---
    ull wv0[32], wv1[32];
    {
        const ulonglong2* wp0 =
            (const ulonglong2*)(Whw + (size_t)jg0 * HH + kq * 64);
        const ulonglong2* wp1 =
            (const ulonglong2*)(Whw + (size_t)jg1 * HH + kq * 64);
#pragma unroll
        for (int i = 0; i < 16; ++i) {
            ulonglong2 a = wp0[i], b = wp1[i];
            wv0[2 * i] = a.x; wv0[2 * i + 1] = a.y;
            wv1[2 * i] = b.x; wv1[2 * i + 1] = b.y;
        }
    }

    for (int i = tid; i < 2 * NB * HH; i += 256)
        ((float*)hsh)[i] = 0.0f;

    if (tid == 0) {
        asm volatile("mbarrier.init.shared.b64 [%0], 8;"
                     :: "r"(smem_u32(&bars[0])) : "memory");
        asm volatile("mbarrier.init.shared.b64 [%0], 8;"
                     :: "r"(smem_u32(&bars[1])) : "memory");
    }

    // ---- assigned update identity: this thread owns e0=2kq, e0+1 ----
    const int e0 = 2 * kq;
    const int rowhalf = kq >> 1;
    const int jrow = rowhalf ? jg1 : jg0;
    const int b0 = e0 & 3;           // batches b0, b0+1
    const float biasr = Whb[jrow];

    // out pointers for the 2 owned (batch,row) streams
    float* po0 = out + (size_t)(bbase + b0)     * TT * HH + jrow;
    float* po1 = out + (size_t)(bbase + b0 + 1) * TT * HH + jrow;

    // gates for t=0
    float gc0 = po0[0], gc1 = po1[0];

    // cluster addresses
    const uint32_t hl = smem_u32(hsh);
    const uint32_t bl0 = smem_u32(&bars[0]);
    uint32_t hr, br0;
    asm("mapa.shared::cluster.u32 %0, %1, %2;"
        : "=r"(hr) : "r"(hl), "r"(rank ^ 1u));
    asm("mapa.shared::cluster.u32 %0, %1, %2;"
        : "=r"(br0) : "r"(bl0), "r"(rank ^ 1u));

    const bool lane0 = ((tid & 31) == 0);

    __syncthreads();
    // one-time: both CTAs' smem init + mbarrier init visible cluster-wide
    asm volatile("barrier.cluster.arrive.aligned;" ::: "memory");
    asm volatile("barrier.cluster.wait.aligned;"   ::: "memory");

    uint32_t ph0 = 0, ph1 = 0;

#pragma unroll 1
    for (int t = 0; t < TT; ++t) {
        const int p = t & 1;
        const int q = p ^ 1;
        const bool not_last = (t + 1 < TT);

        // prefetch gates for t+1 (issued before any waiting)
        float gn0 = 0.f, gn1 = 0.f;
        if (not_last) {
            const size_t o = (size_t)(t + 1) * HH;
            gn0 = po0[o]; gn1 = po1[o];
        }

        // remote-K warps wait for the peer's 8 warp-arrivals into buffer p
        if (t > 0 && remote_k) {
            const uint32_t mb = bl0 + (uint32_t)p * 8u;
            const uint32_t par = p ? ph1 : ph0;
            uint32_t done;
            do {
                asm volatile(
                    "{\n\t.reg .pred P;\n\t"
                    "mbarrier.try_wait.parity.acquire.cluster.shared::cta.b64 "
                    "P, [%1], %2, 0x989680;\n\t"
                    "selp.b32 %0, 1, 0, P;\n\t}"
                    : "=r"(done) : "r"(mb), "r"(par) : "memory");
            } while (!done);
        }
        if (t > 0) { if (p) ph1 ^= 1; else ph0 ^= 1; }

        // ---- matvec over this thread's K-quarter (ratio 4 fma2 : 1 LDS) ----
        const float* hb = &hsh[p][0][kq * 64];
        ull a00 = 0, a01 = 0, a02 = 0, a03 = 0;   // row jg0, batches 0..3
        ull a10 = 0, a11 = 0, a12 = 0, a13 = 0;   // row jg1
#pragma unroll
        for (int i = 0; i < 16; ++i) {
            const ulonglong2 v0 = ((const ulonglong2*)(hb          ))[i];
            const ulonglong2 v1 = ((const ulonglong2*)(hb + HH     ))[i];
            const ulonglong2 v2 = ((const ulonglong2*)(hb + 2 * HH))[i];
            const ulonglong2 v3 = ((const ulonglong2*)(hb + 3 * HH))[i];
            const ull wA0 = wv0[2 * i], wB0 = wv0[2 * i + 1];
            const ull wA1 = wv1[2 * i], wB1 = wv1[2 * i + 1];
            a00 = fma2(wA0, v0.x, a00); a01 = fma2(wA0, v1.x, a01);
            a02 = fma2(wA0, v2.x, a02); a03 = fma2(wA0, v3.x, a03);
            a10 = fma2(wA1, v0.x, a10); a11 = fma2(wA1, v1.x, a11);
            a12 = fma2(wA1, v2.x, a12); a13 = fma2(wA1, v3.x, a13);
            a00 = fma2(wB0, v0.y, a00); a01 = fma2(wB0, v1.y, a01);
            a02 = fma2(wB0, v2.y, a02); a03 = fma2(wB0, v3.y, a03);
            a10 = fma2(wB1, v0.y, a10); a11 = fma2(wB1, v1.y, a11);
            a12 = fma2(wB1, v2.y, a12); a13 = fma2(wB1, v3.y, a13);
        }
        // pair-sum + publish partials: psum[e][kq][j2] (coalesced stores)
        {
            float r[8];
            float2 u;
            u = unpack2(a00); r[0] = u.x + u.y;
            u = unpack2(a01); r[1] = u.x + u.y;
            u = unpack2(a02); r[2] = u.x + u.y;
            u = unpack2(a03); r[3] = u.x + u.y;
            u = unpack2(a10); r[4] = u.x + u.y;
            u = unpack2(a11); r[5] = u.x + u.y;
            u = unpack2(a12); r[6] = u.x + u.y;
            u = unpack2(a13); r[7] = u.x + u.y;
#pragma unroll
            for (int e = 0; e < 8; ++e)
                psum[e][kq][j2] = r[e];
        }
        __syncthreads();   // BAR1: psum visible; also propagates mb-wait

        // ---- assigned reduce + update (coalesced scalar LDS) ----
        const float z0 = ((psum[e0][0][j2]     + psum[e0][1][j2]) +
                          (psum[e0][2][j2]     + psum[e0][3][j2])) + biasr;
        const float z1 = ((psum[e0 + 1][0][j2] + psum[e0 + 1][1][j2]) +
                          (psum[e0 + 1][2][j2] + psum[e0 + 1][3][j2])) + biasr;
        const float th0 = ftanh(z0);
        const float th1 = ftanh(z1);
        const float hp0 = hsh[p][b0][jrow];
        const float hp1 = hsh[p][b0 + 1][jrow];
        const float h0 = fmaf(gc0, hp0 - th0, th0);   // g*h + (1-g)*tanh
        const float h1 = fmaf(gc1, hp1 - th1, th1);
        gc0 = gn0; gc1 = gn1;

        if (not_last) {
            // peer DSMEM stores first (longest flight), then local, then the
            // warp-aggregated early remote arrive.
            const uint32_t ra0 = hr +
                (uint32_t)(((q * NB + b0) * HH + jrow) * 4);
            asm volatile("st.shared::cluster.f32 [%0], %1;"
                         :: "r"(ra0), "f"(h0) : "memory");
            asm volatile("st.shared::cluster.f32 [%0], %1;"
                         :: "r"(ra0 + (uint32_t)(HH * 4)), "f"(h1) : "memory");
            hsh[q][b0][jrow]     = h0;
            hsh[q][b0 + 1][jrow] = h1;
            __syncwarp();
            if (lane0) {
                asm volatile(
                    "mbarrier.arrive.release.cluster.shared::cluster.b64 _, [%0];"
                    :: "r"(br0 + (uint32_t)q * 8u) : "memory");
            }
        }

        // global out stores (gate nothing)
        const size_t ot = (size_t)t * HH;
        po0[ot] = h0;
        po1[ot] = h1;

        __syncthreads();   // BAR2: local h-half ordered for next step
    }

    // Trailing cluster sync: no CTA exits while peer DSMEM traffic may be
    // in flight toward it.
    asm volatile("barrier.cluster.arrive.aligned;" ::: "memory");
    asm volatile("barrier.cluster.wait.aligned;"   ::: "memory");
}

// ---------------------------------------------------------------------------
extern "C" void kernel_launch(void* const* d_in, const int* in_sizes, int n_in,
                              void* d_out, int out_size)
{
    const float* x   = (const float*)d_in[0];  // [B,T,E]
    const float* Wxw = (const float*)d_in[1];  // [H,E]
    const float* Wxb = (const float*)d_in[2];  // [H]
    const float* Whw = (const float*)d_in[3];  // [H,H]
    const float* Whb = (const float*)d_in[4];  // [H]
    float* out = (float*)d_out;                // [B,T,H]

    dim3 g1(BSZ * TT / 128, HH / 128);
    gates_kernel<<<g1, 256>>>(x, Wxw, Wxb, out);

    mgu_scan<<<(BSZ / NB) * 2, 256>>>(Whw, Whb, out);
}